// round 2
// baseline (speedup 1.0000x reference)
#include <cuda_runtime.h>
#include <math_constants.h>

// Problem constants (fixed by reference: B=16, T=2048, D=256, K=4096)
#define N_TOK 32768
#define DIM   256
#define KCB   4096

// Output layout in d_out (f32):
//   [0]                      c_loss
//   [1 .. 1+N*D)             quantized (straight-through value)   << starts at +4B: NOT 16B-aligned
//   [1+N*D .. 1+N*D+N)       encoding_index cast to float

// Scratch (device globals; no allocations allowed)
__device__ float g_S[N_TOK];     // per-token sum of squares (fp32, sequential order)
__device__ float g_c[KCB];       // per-code sum of squares
__device__ int   g_idx[N_TOK];   // argmin index
__device__ float g_loss[N_TOK];  // per-token sum of (q-x)^2

// ---------------------------------------------------------------------------
// Kernel 1: per-row sums of squares with exact fp32 rounding (mul rounds, add
// rounds, strictly sequential index order — mimics a scalar reduction).
// ---------------------------------------------------------------------------
__global__ void prep_kernel(const float* __restrict__ X, const float* __restrict__ E) {
    int i = blockIdx.x * blockDim.x + threadIdx.x;
    if (i < N_TOK) {
        const float4* row = reinterpret_cast<const float4*>(X + (size_t)i * DIM);
        float s = 0.0f;
        #pragma unroll 8
        for (int j = 0; j < DIM / 4; j++) {
            float4 v = row[j];
            s = __fadd_rn(s, __fmul_rn(v.x, v.x));
            s = __fadd_rn(s, __fmul_rn(v.y, v.y));
            s = __fadd_rn(s, __fmul_rn(v.z, v.z));
            s = __fadd_rn(s, __fmul_rn(v.w, v.w));
        }
        g_S[i] = s;
    }
    if (i < KCB) {
        const float4* row = reinterpret_cast<const float4*>(E + (size_t)i * DIM);
        float s = 0.0f;
        #pragma unroll 8
        for (int j = 0; j < DIM / 4; j++) {
            float4 v = row[j];
            s = __fadd_rn(s, __fmul_rn(v.x, v.x));
            s = __fadd_rn(s, __fmul_rn(v.y, v.y));
            s = __fadd_rn(s, __fmul_rn(v.z, v.z));
            s = __fadd_rn(s, __fmul_rn(v.w, v.w));
        }
        g_c[i] = s;
    }
}

// ---------------------------------------------------------------------------
// Kernel 2: fused fp32 GEMM (X @ E^T) + argmin over codes.
// Tile: BM=64 tokens x BN=128 codes, BK=16, 128 threads, 8x8 microtile.
// d2 replicates the reference rounding chain:
//   m   = fp32 dot (accumulation order free — affects <1 ulp of d2 grid)
//   t   = fl(S - 2*m)   (single rounding, via fmaf(-2, m, S))
//   d2  = fl(t + c)
// Argmin: lexicographic (d2, index) min => first-index tie rule, order-free.
// ---------------------------------------------------------------------------
#define BM 64
#define BN 128
#define BK 16
#define NCHUNK (DIM / BK)   // 16
#define NTILE  (KCB / BN)   // 32

__global__ __launch_bounds__(128) void argmin_kernel(const float* __restrict__ X,
                                                     const float* __restrict__ E,
                                                     float* __restrict__ out_idx_f) {
    __shared__ __align__(16) float Xs[2][BK][BM];
    __shared__ __align__(16) float Es[2][BK][BN];

    const int tid = threadIdx.x;
    const int tx = tid & 15;        // code direction, 16 threads
    const int ty = tid >> 4;        // token direction, 8 threads
    const int nb = blockIdx.x * BM; // token base

    // Per-thread token rows: nb + ty*8 + i
    float sreg[8];
    #pragma unroll
    for (int i = 0; i < 8; i++) sreg[i] = g_S[nb + ty * 8 + i];

    float best[8];
    int   bidx[8];
    #pragma unroll
    for (int i = 0; i < 8; i++) { best[i] = CUDART_INF_F; bidx[i] = 0x7fffffff; }

    // Per-thread global-load coordinates
    // X chunk: 64 tokens x 16 dims = 256 float4; thread handles q=tid, q=tid+128
    const int xq0_tok = tid >> 2, xq0_d = (tid & 3) * 4;
    const int xq1_tok = (tid + 128) >> 2, xq1_d = ((tid + 128) & 3) * 4;
    // E chunk: 128 codes x 16 dims = 512 float4; thread handles q=tid+j*128
    // code = q>>2, dsub = (q&3)*4

    for (int ct = 0; ct < NTILE; ct++) {
        float acc[8][8];
        #pragma unroll
        for (int i = 0; i < 8; i++)
            #pragma unroll
            for (int j = 0; j < 8; j++) acc[i][j] = 0.0f;

        // ---- prologue: load chunk 0 into buffer 0 ----
        float4 xr0, xr1, er[4];
        {
            const int dc = 0;
            xr0 = *reinterpret_cast<const float4*>(X + (size_t)(nb + xq0_tok) * DIM + dc * BK + xq0_d);
            xr1 = *reinterpret_cast<const float4*>(X + (size_t)(nb + xq1_tok) * DIM + dc * BK + xq1_d);
            #pragma unroll
            for (int j = 0; j < 4; j++) {
                int q = tid + j * 128;
                er[j] = *reinterpret_cast<const float4*>(E + (size_t)(ct * BN + (q >> 2)) * DIM + dc * BK + (q & 3) * 4);
            }
            // store to buffer 0 (transposed [dim][row])
            Xs[0][xq0_d + 0][xq0_tok] = xr0.x; Xs[0][xq0_d + 1][xq0_tok] = xr0.y;
            Xs[0][xq0_d + 2][xq0_tok] = xr0.z; Xs[0][xq0_d + 3][xq0_tok] = xr0.w;
            Xs[0][xq1_d + 0][xq1_tok] = xr1.x; Xs[0][xq1_d + 1][xq1_tok] = xr1.y;
            Xs[0][xq1_d + 2][xq1_tok] = xr1.z; Xs[0][xq1_d + 3][xq1_tok] = xr1.w;
            #pragma unroll
            for (int j = 0; j < 4; j++) {
                int q = tid + j * 128;
                int c = q >> 2, d = (q & 3) * 4;
                Es[0][d + 0][c] = er[j].x; Es[0][d + 1][c] = er[j].y;
                Es[0][d + 2][c] = er[j].z; Es[0][d + 3][c] = er[j].w;
            }
        }
        __syncthreads();

        int p = 0;
        for (int dc = 0; dc < NCHUNK; dc++) {
            // prefetch next chunk to registers
            if (dc < NCHUNK - 1) {
                const int dn = dc + 1;
                xr0 = *reinterpret_cast<const float4*>(X + (size_t)(nb + xq0_tok) * DIM + dn * BK + xq0_d);
                xr1 = *reinterpret_cast<const float4*>(X + (size_t)(nb + xq1_tok) * DIM + dn * BK + xq1_d);
                #pragma unroll
                for (int j = 0; j < 4; j++) {
                    int q = tid + j * 128;
                    er[j] = *reinterpret_cast<const float4*>(E + (size_t)(ct * BN + (q >> 2)) * DIM + dn * BK + (q & 3) * 4);
                }
            }
            // compute on buffer p
            #pragma unroll
            for (int kk = 0; kk < BK; kk++) {
                float4 a0 = *reinterpret_cast<const float4*>(&Xs[p][kk][ty * 8]);
                float4 a1 = *reinterpret_cast<const float4*>(&Xs[p][kk][ty * 8 + 4]);
                float4 b0 = *reinterpret_cast<const float4*>(&Es[p][kk][tx * 8]);
                float4 b1 = *reinterpret_cast<const float4*>(&Es[p][kk][tx * 8 + 4]);
                float a[8] = {a0.x, a0.y, a0.z, a0.w, a1.x, a1.y, a1.z, a1.w};
                float b[8] = {b0.x, b0.y, b0.z, b0.w, b1.x, b1.y, b1.z, b1.w};
                #pragma unroll
                for (int i = 0; i < 8; i++)
                    #pragma unroll
                    for (int j = 0; j < 8; j++)
                        acc[i][j] = fmaf(a[i], b[j], acc[i][j]);
            }
            // store prefetched chunk into the other buffer
            if (dc < NCHUNK - 1) {
                int np = p ^ 1;
                Xs[np][xq0_d + 0][xq0_tok] = xr0.x; Xs[np][xq0_d + 1][xq0_tok] = xr0.y;
                Xs[np][xq0_d + 2][xq0_tok] = xr0.z; Xs[np][xq0_d + 3][xq0_tok] = xr0.w;
                Xs[np][xq1_d + 0][xq1_tok] = xr1.x; Xs[np][xq1_d + 1][xq1_tok] = xr1.y;
                Xs[np][xq1_d + 2][xq1_tok] = xr1.z; Xs[np][xq1_d + 3][xq1_tok] = xr1.w;
                #pragma unroll
                for (int j = 0; j < 4; j++) {
                    int q = tid + j * 128;
                    int c = q >> 2, d = (q & 3) * 4;
                    Es[np][d + 0][c] = er[j].x; Es[np][d + 1][c] = er[j].y;
                    Es[np][d + 2][c] = er[j].z; Es[np][d + 3][c] = er[j].w;
                }
                __syncthreads();
                p = np;
            }
        }

        // ---- epilogue: d2 chain + running argmin (codes ascend) ----
        float cj[8];
        #pragma unroll
        for (int j = 0; j < 8; j++) cj[j] = __ldg(&g_c[ct * BN + tx * 8 + j]);
        #pragma unroll
        for (int i = 0; i < 8; i++) {
            #pragma unroll
            for (int j = 0; j < 8; j++) {
                float t  = fmaf(-2.0f, acc[i][j], sreg[i]); // fl(S - 2m)
                float d2 = __fadd_rn(t, cj[j]);             // fl(t + c)
                int code = ct * BN + tx * 8 + j;
                if (d2 < best[i]) { best[i] = d2; bidx[i] = code; }
            }
        }
        __syncthreads(); // protect smem reuse across tiles
    }

    // Cross-thread reduction over tx (lanes differing in bits 0..3 of lane id).
    // Lexicographic (val, idx) min is associative; ties -> lowest index.
    #pragma unroll
    for (int off = 8; off >= 1; off >>= 1) {
        #pragma unroll
        for (int i = 0; i < 8; i++) {
            float ov = __shfl_xor_sync(0xffffffffu, best[i], off);
            int   oi = __shfl_xor_sync(0xffffffffu, bidx[i], off);
            if (ov < best[i] || (ov == best[i] && oi < bidx[i])) {
                best[i] = ov; bidx[i] = oi;
            }
        }
    }
    if (tx == 0) {
        #pragma unroll
        for (int i = 0; i < 8; i++) {
            int tok = nb + ty * 8 + i;
            g_idx[tok] = bidx[i];
            out_idx_f[tok] = (float)bidx[i];
        }
    }
}

// ---------------------------------------------------------------------------
// Kernel 3: gather + straight-through output + per-token loss.
// Replicates bitwise: diff = fl(q - x); out = fl(x + diff); loss term fl(diff^2).
// One warp per token. Inputs are read with aligned float4; the quantized
// output region starts at d_out+1 (4-byte aligned ONLY), so stores are scalar.
// ---------------------------------------------------------------------------
__global__ void output_kernel(const float* __restrict__ X, const float* __restrict__ E,
                              float* __restrict__ out_q) {
    int warp = (blockIdx.x * blockDim.x + threadIdx.x) >> 5;
    int lane = threadIdx.x & 31;
    if (warp >= N_TOK) return;
    int code = g_idx[warp];
    const float4* xr = reinterpret_cast<const float4*>(X + (size_t)warp * DIM);
    const float4* er = reinterpret_cast<const float4*>(E + (size_t)code * DIM);
    float* qr = out_q + (size_t)warp * DIM;  // 4B-aligned only

    float ls = 0.0f;
    #pragma unroll
    for (int j = lane; j < DIM / 4; j += 32) {
        float4 x = xr[j], e = er[j];
        float4 d, o;
        d.x = __fadd_rn(e.x, -x.x); d.y = __fadd_rn(e.y, -x.y);
        d.z = __fadd_rn(e.z, -x.z); d.w = __fadd_rn(e.w, -x.w);
        ls = __fadd_rn(ls, __fmul_rn(d.x, d.x));
        ls = __fadd_rn(ls, __fmul_rn(d.y, d.y));
        ls = __fadd_rn(ls, __fmul_rn(d.z, d.z));
        ls = __fadd_rn(ls, __fmul_rn(d.w, d.w));
        o.x = __fadd_rn(x.x, d.x); o.y = __fadd_rn(x.y, d.y);
        o.z = __fadd_rn(x.z, d.z); o.w = __fadd_rn(x.w, d.w);
        qr[j * 4 + 0] = o.x;   // scalar STG.32: region is only 4B-aligned
        qr[j * 4 + 1] = o.y;
        qr[j * 4 + 2] = o.z;
        qr[j * 4 + 3] = o.w;
    }
    #pragma unroll
    for (int off = 16; off >= 1; off >>= 1)
        ls = __fadd_rn(ls, __shfl_xor_sync(0xffffffffu, ls, off));
    if (lane == 0) g_loss[warp] = ls;
}

// ---------------------------------------------------------------------------
// Kernel 4: deterministic double-precision loss reduce -> c_loss.
// ---------------------------------------------------------------------------
__global__ void finalize_kernel(float* __restrict__ out) {
    __shared__ double sh[256];
    double s = 0.0;
    for (int i = threadIdx.x; i < N_TOK; i += 256) s += (double)g_loss[i];
    sh[threadIdx.x] = s;
    __syncthreads();
    for (int off = 128; off >= 1; off >>= 1) {
        if (threadIdx.x < off) sh[threadIdx.x] += sh[threadIdx.x + off];
        __syncthreads();
    }
    if (threadIdx.x == 0)
        out[0] = (float)(0.5 * sh[0] / ((double)N_TOK * (double)DIM));
}

// ---------------------------------------------------------------------------
extern "C" void kernel_launch(void* const* d_in, const int* in_sizes, int n_in,
                              void* d_out, int out_size) {
    const float* X = (const float*)d_in[0];   // embedding_tokens [N, D]
    const float* E = (const float*)d_in[1];   // embeddings       [K, D]
    float* out = (float*)d_out;
    float* out_q   = out + 1;
    float* out_idx = out + 1 + (size_t)N_TOK * DIM;

    prep_kernel<<<(N_TOK + 255) / 256, 256>>>(X, E);
    argmin_kernel<<<N_TOK / BM, 128>>>(X, E, out_idx);
    output_kernel<<<(N_TOK * 32 + 255) / 256, 256>>>(X, E, out_q);
    finalize_kernel<<<1, 256>>>(out);
}